// round 16
// baseline (speedup 1.0000x reference)
#include <cuda_runtime.h>
#include <cuda_fp16.h>
#include <cstdint>
#include <math.h>

// ---------------- problem constants ----------------
#define BB 4
#define TT 2048
#define DD 1024
#define HH 16
#define HD 64
#define FF 4096
#define MM (BB*TT)          // 8192 rows
#define MQ (MM/4)           // 2048 rows (1 batch per chain)

// ---------------- scratch arena (float units; half buffers cast in) ----------------
#define OFF_H     0                     // [MM,DD] half
#define OFF_QKV   4194304               // [MM,3DD] half
#define OFF_CTX   16777216              // [MM,DD] half
#define OFF_X1    20971520              // [MM,DD] float
#define OFF_H2    29360128              // [MM,DD] half
#define OFF_FF    33554432              // [MM,FF] half
#define OFF_WQKV  50331648              // [3DD,DD] half (transposed)
#define OFF_BQKV  51904512              // [3DD] float
#define OFF_WO    51907584              // [DD,DD] half (transposed)
#define OFF_W1    52431872              // [FF,DD] half (transposed)
#define OFF_W2    54529024              // [DD,FF] half (transposed)
#define SCRATCH_TOTAL 56626176

__device__ float d_scratch[SCRATCH_TOTAL];

// ---------------- helpers ----------------
__device__ __forceinline__ uint32_t smem_u32(const void* p) {
    uint32_t a;
    asm("{ .reg .u64 t; cvta.to.shared.u64 t, %1; cvt.u32.u64 %0, t; }" : "=r"(a) : "l"(p));
    return a;
}
__device__ __forceinline__ void cpasync16(uint32_t saddr, const void* g) {
    asm volatile("cp.async.cg.shared.global [%0], [%1], 16;" :: "r"(saddr), "l"(g));
}
__device__ __forceinline__ void ldsm_x4(uint32_t* r, uint32_t addr) {
    asm volatile("ldmatrix.sync.aligned.m8n8.x4.shared.b16 {%0,%1,%2,%3}, [%4];"
                 : "=r"(r[0]), "=r"(r[1]), "=r"(r[2]), "=r"(r[3]) : "r"(addr));
}
__device__ __forceinline__ void ldsm_x4_t(uint32_t* r, uint32_t addr) {
    asm volatile("ldmatrix.sync.aligned.m8n8.x4.trans.shared.b16 {%0,%1,%2,%3}, [%4];"
                 : "=r"(r[0]), "=r"(r[1]), "=r"(r[2]), "=r"(r[3]) : "r"(addr));
}
__device__ __forceinline__ void mma_f16(float* d, const uint32_t* a, uint32_t b0, uint32_t b1) {
    asm volatile("mma.sync.aligned.m16n8k16.row.col.f32.f16.f16.f32 "
                 "{%0,%1,%2,%3}, {%4,%5,%6,%7}, {%8,%9}, {%0,%1,%2,%3};"
                 : "+f"(d[0]), "+f"(d[1]), "+f"(d[2]), "+f"(d[3])
                 : "r"(a[0]), "r"(a[1]), "r"(a[2]), "r"(a[3]), "r"(b0), "r"(b1));
}
__device__ __forceinline__ uint32_t f22h2(float a, float b) {
    __half2 h = __floats2half2_rn(a, b);
    return *(uint32_t*)&h;
}
#define SWZ128(o) ((o) ^ (((o) >> 3) & 0x70))
#define QSCALE (0.125f * 1.44269504088896341f)   // 1/sqrt(HD) * log2(e)

// ---------------- fast 64x64-tile transpose to half ----------------
__global__ __launch_bounds__(256)
void transpose_half(const float* __restrict__ in, __half* __restrict__ out, int R, int C) {
    __shared__ float t[64][65];
    int c0 = blockIdx.x * 64, r0 = blockIdx.y * 64;
    int tid = threadIdx.x;
#pragma unroll
    for (int i = 0; i < 4; i++) {
        int idx = tid + i * 256;
        int r = idx >> 4, q = idx & 15;
        float4 v = *(const float4*)(in + (size_t)(r0 + r) * C + c0 + q * 4);
        t[r][q * 4 + 0] = v.x; t[r][q * 4 + 1] = v.y;
        t[r][q * 4 + 2] = v.z; t[r][q * 4 + 3] = v.w;
    }
    __syncthreads();
    int c = tid >> 2;
    int jb = (tid & 3) * 16;
    __half* orow = out + (size_t)(c0 + c) * R + r0 + jb;
#pragma unroll
    for (int u = 0; u < 8; u++) {
        *(uint32_t*)(orow + u * 2) = f22h2(t[jb + u * 2][c], t[jb + u * 2 + 1][c]);
    }
}

// ---------------- QKV weight pack + bias; Q scaled by QSCALE ----------------
__global__ __launch_bounds__(256)
void pack_qkvT(const float* __restrict__ Wq, const float* __restrict__ Wk,
               const float* __restrict__ Wv, __half* __restrict__ WqkvT,
               const float* __restrict__ bq, const float* __restrict__ bk,
               const float* __restrict__ bv, float* __restrict__ bqkv) {
    __shared__ float t[64][65];
    int n0 = blockIdx.y * 64;
    int d0 = blockIdx.x * 64;
    int proj = n0 >> 10;
    int h = (n0 & 1023) >> 6;
    const float* W = (proj == 0) ? Wq : ((proj == 1) ? Wk : Wv);
    float scale = (proj == 0) ? QSCALE : 1.0f;
    const float* base = W + (size_t)h * DD * HD;
    int tid = threadIdx.x;

    if (blockIdx.x == 0 && tid < 64) {
        const float* b = (proj == 0) ? bq : ((proj == 1) ? bk : bv);
        bqkv[n0 + tid] = b[(n0 & 1023) + tid] * scale;
    }

#pragma unroll
    for (int i = 0; i < 4; i++) {
        int idx = tid + i * 256;
        int r = idx >> 4, q = idx & 15;
        float4 v = *(const float4*)(base + (size_t)(d0 + r) * HD + q * 4);
        t[r][q * 4 + 0] = v.x * scale; t[r][q * 4 + 1] = v.y * scale;
        t[r][q * 4 + 2] = v.z * scale; t[r][q * 4 + 3] = v.w * scale;
    }
    __syncthreads();
    int c = tid >> 2;
    int jb = (tid & 3) * 16;
    __half* orow = WqkvT + (size_t)(n0 + c) * DD + d0 + jb;
#pragma unroll
    for (int u = 0; u < 8; u++) {
        *(uint32_t*)(orow + u * 2) = f22h2(t[jb + u * 2][c], t[jb + u * 2 + 1][c]);
    }
}

// ---------------- LayerNorm: fp32 in, half out ----------------
__global__ __launch_bounds__(256)
void layernorm_kernel(const float* __restrict__ x, const float* __restrict__ g,
                      const float* __restrict__ bta, __half* __restrict__ out) {
    __shared__ float red[16];
    int row = blockIdx.x;
    const float* xr = x + (size_t)row * DD;
    float v[4];
    float s = 0.f, s2 = 0.f;
#pragma unroll
    for (int i = 0; i < 4; i++) {
        v[i] = xr[threadIdx.x + i * 256];
        s += v[i];
        s2 += v[i] * v[i];
    }
#pragma unroll
    for (int o = 16; o > 0; o >>= 1) {
        s  += __shfl_xor_sync(0xffffffffu, s,  o);
        s2 += __shfl_xor_sync(0xffffffffu, s2, o);
    }
    int w = threadIdx.x >> 5;
    if ((threadIdx.x & 31) == 0) { red[w] = s; red[w + 8] = s2; }
    __syncthreads();
    s = 0.f; s2 = 0.f;
#pragma unroll
    for (int i = 0; i < 8; i++) { s += red[i]; s2 += red[i + 8]; }
    float mu  = s * (1.f / (float)DD);
    float var = s2 * (1.f / (float)DD) - mu * mu;
    float inv = rsqrtf(var + 1e-5f);
#pragma unroll
    for (int i = 0; i < 4; i++) {
        int c = threadIdx.x + i * 256;
        out[(size_t)row * DD + c] = __float2half_rn((v[i] - mu) * inv * g[c] + bta[c]);
    }
}

// ---------------- fp16 mma GEMM: BM=64,BN=128,BK=64, 128 thr, 2-stage, 4 CTA/SM ----------
#define GSTAGES 2
#define GBM 64
#define GBN 128
#define GBK 64
#define A_ST_BYTES (GBM * 128)           // 8192
#define B_ST_BYTES (GBN * 128)           // 16384
#define GEMM_SMEM (GSTAGES * (A_ST_BYTES + B_ST_BYTES))   // 49152

template <int EPI>
__global__ __launch_bounds__(128, 4)
void tc_gemm(const __half* __restrict__ A, const __half* __restrict__ BT,
             const float* __restrict__ bias, const float* __restrict__ res,
             void* __restrict__ Cout, int M, int N, int K) {
    extern __shared__ __align__(128) char smem[];
    uint32_t sb = smem_u32(smem);
    const uint32_t sA0 = sb;
    const uint32_t sB0 = sb + GSTAGES * A_ST_BYTES;

    int tid = threadIdx.x;
    int lane = tid & 31;
    int wn = tid >> 5;
    int bm = blockIdx.y * GBM, bn = blockIdx.x * GBN;

    int rowin = lane & 7;
    int quad  = lane >> 3;
    int lrow  = (quad & 1) * 8 + rowin;
    int lkoff = (quad >> 1) * 16;

    float acc[16][4];
#pragma unroll
    for (int i = 0; i < 16; i++)
#pragma unroll
        for (int j = 0; j < 4; j++) acc[i][j] = 0.f;

    const int NC = K / GBK;

    auto load_chunk = [&](int c) {
        int s = c & 1;
        uint32_t sA = sA0 + s * A_ST_BYTES;
        uint32_t sB = sB0 + s * B_ST_BYTES;
        const __half* Ab = A + (size_t)bm * K + c * GBK;
        const __half* Bb = BT + (size_t)bn * K + c * GBK;
#pragma unroll
        for (int i = 0; i < 4; i++) {
            int idx = tid + i * 128;
            int r = idx >> 3, q = idx & 7;
            cpasync16(sA + SWZ128((uint32_t)(r * 128 + q * 16)), Ab + (size_t)r * K + q * 8);
        }
#pragma unroll
        for (int i = 0; i < 8; i++) {
            int idx = tid + i * 128;
            int r = idx >> 3, q = idx & 7;
            cpasync16(sB + SWZ128((uint32_t)(r * 128 + q * 16)), Bb + (size_t)r * K + q * 8);
        }
        asm volatile("cp.async.commit_group;" ::: "memory");
    };

    load_chunk(0);
    load_chunk(1);

    for (int c = 0; c < NC; c++) {
        if (c + 1 < NC) asm volatile("cp.async.wait_group 1;" ::: "memory");
        else            asm volatile("cp.async.wait_group 0;" ::: "memory");
        __syncthreads();

        int s = c & 1;
        uint32_t aT = sA0 + s * A_ST_BYTES;
        uint32_t bT = sB0 + s * B_ST_BYTES;
#pragma unroll
        for (int ks = 0; ks < 4; ks++) {
            uint32_t af[4][4];
#pragma unroll
            for (int mi = 0; mi < 4; mi++) {
                uint32_t off = (uint32_t)((mi * 16 + lrow) * 128 + lkoff + ks * 32);
                ldsm_x4(af[mi], aT + SWZ128(off));
            }
            uint32_t bf[2][4];
#pragma unroll
            for (int np = 0; np < 2; np++) {
                uint32_t off = (uint32_t)((wn * 32 + np * 16 + lrow) * 128 + lkoff + ks * 32);
                ldsm_x4(bf[np], bT + SWZ128(off));
            }
#pragma unroll
            for (int mi = 0; mi < 4; mi++)
#pragma unroll
                for (int ni = 0; ni < 4; ni++) {
                    int np = ni >> 1, sub = ni & 1;
                    mma_f16(acc[mi * 4 + ni], af[mi], bf[np][sub], bf[np][sub + 2]);
                }
        }
        __syncthreads();
        if (c + 2 < NC) load_chunk(c + 2);
    }

#pragma unroll
    for (int mi = 0; mi < 4; mi++) {
        int r0 = bm + mi * 16 + (lane >> 2);
#pragma unroll
        for (int ni = 0; ni < 4; ni++) {
            int col = bn + wn * 32 + ni * 8 + 2 * (lane & 3);
            float2 bb = *(const float2*)(bias + col);
#pragma unroll
            for (int half_ = 0; half_ < 2; half_++) {
                int r = r0 + half_ * 8;
                float v0 = acc[mi * 4 + ni][half_ * 2 + 0] + bb.x;
                float v1 = acc[mi * 4 + ni][half_ * 2 + 1] + bb.y;
                if (EPI == 1) {
                    float2 rr = *(const float2*)(res + (size_t)r * N + col);
                    v0 += rr.x; v1 += rr.y;
                    *(float2*)((float*)Cout + (size_t)r * N + col) = make_float2(v0, v1);
                } else if (EPI == 2) {
                    v0 = 0.5f * v0 * (1.0f + erff(v0 * 0.70710678118654752f));
                    v1 = 0.5f * v1 * (1.0f + erff(v1 * 0.70710678118654752f));
                    *(uint32_t*)((__half*)Cout + (size_t)r * N + col) = f22h2(v0, v1);
                } else {
                    *(uint32_t*)((__half*)Cout + (size_t)r * N + col) = f22h2(v0, v1);
                }
            }
        }
    }
}

// ---------------- Flash attention: base-2 softmax, LPT, batch-offset ------------------------
#define ATTN_SMEM (8192 + 2 * 16384)
#define SQ_OFF 0
#define SK_OFF(s) (8192 + (s) * 16384)
#define SV_OFF(s) (16384 + (s) * 16384)

__global__ __launch_bounds__(128)
void attn_kernel(const __half* __restrict__ qkv, __half* __restrict__ ctx, int b0) {
    extern __shared__ __align__(128) char smem[];
    uint32_t sb = smem_u32(smem);

    int qt = gridDim.x - 1 - blockIdx.x;    // LPT: longest tiles first
    int h = blockIdx.y, b = blockIdx.z + b0;
    int tid = threadIdx.x;
    int lane = tid & 31;
    int warp = tid >> 5;
    int q0 = qt * 64;

    int rowin = lane & 7;
    int quad  = lane >> 3;
    int lrow  = (quad & 1) * 8 + rowin;
    int lkoff = (quad >> 1) * 16;
    int g = lane >> 2;
    int t2 = 2 * (lane & 3);

    const __half* qbase = qkv + (size_t)(b * TT + q0) * 3072 + h * 64;
#pragma unroll
    for (int i = 0; i < 4; i++) {
        int idx = tid + i * 128;
        int r = idx >> 3, q = idx & 7;
        cpasync16(sb + SQ_OFF + SWZ128((uint32_t)(r * 128 + q * 16)),
                  qbase + (size_t)r * 3072 + q * 8);
    }
    auto load_kv = [&](int jt) {
        int s = jt & 1;
        const __half* kb = qkv + (size_t)(b * TT + jt * 64) * 3072 + 1024 + h * 64;
        const __half* vb = kb + 1024;
#pragma unroll
        for (int i = 0; i < 4; i++) {
            int idx = tid + i * 128;
            int r = idx >> 3, q = idx & 7;
            uint32_t off = SWZ128((uint32_t)(r * 128 + q * 16));
            cpasync16(sb + SK_OFF(s) + off, kb + (size_t)r * 3072 + q * 8);
            cpasync16(sb + SV_OFF(s) + off, vb + (size_t)r * 3072 + q * 8);
        }
        asm volatile("cp.async.commit_group;" ::: "memory");
    };
    load_kv(0);

    float m0 = -1e30f, m1 = -1e30f, l0 = 0.f, l1 = 0.f;
    float accO[8][4];
#pragma unroll
    for (int i = 0; i < 8; i++)
#pragma unroll
        for (int j = 0; j < 4; j++) accO[i][j] = 0.f;

    uint32_t qaf[4][4];
    bool qloaded = false;

    for (int jt = 0; jt <= qt; jt++) {
        if (jt + 1 <= qt) load_kv(jt + 1);
        if (jt + 1 <= qt) asm volatile("cp.async.wait_group 1;" ::: "memory");
        else              asm volatile("cp.async.wait_group 0;" ::: "memory");
        __syncthreads();

        int s = jt & 1;
        uint32_t kT = sb + SK_OFF(s);
        uint32_t vT = sb + SV_OFF(s);

        if (!qloaded) {
            qloaded = true;
#pragma unroll
            for (int ks = 0; ks < 4; ks++) {
                uint32_t off = (uint32_t)((warp * 16 + lrow) * 128 + lkoff + ks * 32);
                ldsm_x4(qaf[ks], sb + SQ_OFF + SWZ128(off));
            }
        }

        float sc[8][4];
#pragma unroll
        for (int i = 0; i < 8; i++)
#pragma unroll
            for (int j = 0; j < 4; j++) sc[i][j] = 0.f;
#pragma unroll
        for (int ks = 0; ks < 4; ks++) {
#pragma unroll
            for (int np = 0; np < 4; np++) {
                uint32_t bf[4];
                uint32_t off = (uint32_t)((np * 16 + lrow) * 128 + lkoff + ks * 32);
                ldsm_x4(bf, kT + SWZ128(off));
                mma_f16(sc[np * 2 + 0], qaf[ks], bf[0], bf[2]);
                mma_f16(sc[np * 2 + 1], qaf[ks], bf[1], bf[3]);
            }
        }

        if (jt == qt) {
            int r0g = warp * 16 + g, r1g = r0g + 8;
#pragma unroll
            for (int i = 0; i < 8; i++) {
                int c0 = i * 8 + t2;
                if (c0     > r0g) sc[i][0] = -1e30f;
                if (c0 + 1 > r0g) sc[i][1] = -1e30f;
                if (c0     > r1g) sc[i][2] = -1e30f;
                if (c0 + 1 > r1g) sc[i][3] = -1e30f;
            }
        }

        float mx0 = -1e30f, mx1 = -1e30f;
#pragma unroll
        for (int i = 0; i < 8; i++) {
            mx0 = fmaxf(mx0, fmaxf(sc[i][0], sc[i][1]));
            mx1 = fmaxf(mx1, fmaxf(sc[i][2], sc[i][3]));
        }
#pragma unroll
        for (int o = 1; o <= 2; o <<= 1) {
            mx0 = fmaxf(mx0, __shfl_xor_sync(0xffffffffu, mx0, o));
            mx1 = fmaxf(mx1, __shfl_xor_sync(0xffffffffu, mx1, o));
        }
        float mn0 = fmaxf(m0, mx0), mn1 = fmaxf(m1, mx1);
        float sc0 = exp2f(m0 - mn0), sc1 = exp2f(m1 - mn1);
        float sum0 = 0.f, sum1 = 0.f;
        uint32_t ph[8][2];
#pragma unroll
        for (int i = 0; i < 8; i++) {
            float p0 = exp2f(sc[i][0] - mn0);
            float p1 = exp2f(sc[i][1] - mn0);
            float p2 = exp2f(sc[i][2] - mn1);
            float p3 = exp2f(sc[i][3] - mn1);
            sum0 += p0 + p1; sum1 += p2 + p3;
            ph[i][0] = f22h2(p0, p1);
            ph[i][1] = f22h2(p2, p3);
        }
#pragma unroll
        for (int o = 1; o <= 2; o <<= 1) {
            sum0 += __shfl_xor_sync(0xffffffffu, sum0, o);
            sum1 += __shfl_xor_sync(0xffffffffu, sum1, o);
        }
        l0 = l0 * sc0 + sum0; l1 = l1 * sc1 + sum1;
        m0 = mn0; m1 = mn1;
#pragma unroll
        for (int i = 0; i < 8; i++) {
            accO[i][0] *= sc0; accO[i][1] *= sc0;
            accO[i][2] *= sc1; accO[i][3] *= sc1;
        }

#pragma unroll
        for (int kt = 0; kt < 4; kt++) {
            uint32_t pa[4] = { ph[2 * kt][0], ph[2 * kt][1], ph[2 * kt + 1][0], ph[2 * kt + 1][1] };
#pragma unroll
            for (int dg = 0; dg < 4; dg++) {
                uint32_t bf[4];
                uint32_t off = (uint32_t)((kt * 16 + lrow) * 128 + dg * 32 + lkoff);
                ldsm_x4_t(bf, vT + SWZ128(off));
                mma_f16(accO[dg * 2 + 0], pa, bf[0], bf[1]);
                mma_f16(accO[dg * 2 + 1], pa, bf[2], bf[3]);
            }
        }
        __syncthreads();
    }

    float inv0 = 1.f / l0, inv1 = 1.f / l1;
    int r0 = b * TT + q0 + warp * 16 + g;
#pragma unroll
    for (int i = 0; i < 8; i++) {
        int col = h * 64 + i * 8 + t2;
        *(uint32_t*)(ctx + (size_t)r0 * DD + col)       = f22h2(accO[i][0] * inv0, accO[i][1] * inv0);
        *(uint32_t*)(ctx + (size_t)(r0 + 8) * DD + col) = f22h2(accO[i][2] * inv1, accO[i][3] * inv1);
    }
}

// ---------------- launcher: four per-batch chains on TWO compute streams ----------------
extern "C" void kernel_launch(void* const* d_in, const int* in_sizes, int n_in,
                              void* d_out, int out_size) {
    const float* x     = (const float*)d_in[0];
    const float* ln1_g = (const float*)d_in[2];
    const float* ln1_b = (const float*)d_in[3];
    const float* Wq    = (const float*)d_in[4];
    const float* bq    = (const float*)d_in[5];
    const float* Wk    = (const float*)d_in[6];
    const float* bk    = (const float*)d_in[7];
    const float* Wv    = (const float*)d_in[8];
    const float* bv    = (const float*)d_in[9];
    const float* Wo    = (const float*)d_in[10];
    const float* bo    = (const float*)d_in[11];
    const float* ln2_g = (const float*)d_in[12];
    const float* ln2_b = (const float*)d_in[13];
    const float* W1    = (const float*)d_in[14];
    const float* b1    = (const float*)d_in[15];
    const float* W2    = (const float*)d_in[16];
    const float* b2    = (const float*)d_in[17];
    float* out = (float*)d_out;

    float* scratch = nullptr;
    cudaGetSymbolAddress((void**)&scratch, d_scratch);
    __half* s_h    = (__half*)(scratch + OFF_H);
    __half* s_qkv  = (__half*)(scratch + OFF_QKV);
    __half* s_ctx  = (__half*)(scratch + OFF_CTX);
    float*  s_x1   = scratch + OFF_X1;
    __half* s_h2   = (__half*)(scratch + OFF_H2);
    __half* s_ff   = (__half*)(scratch + OFF_FF);
    __half* s_Wqkv = (__half*)(scratch + OFF_WQKV);
    float*  s_bqkv = scratch + OFF_BQKV;
    __half* s_Wo   = (__half*)(scratch + OFF_WO);
    __half* s_W1   = (__half*)(scratch + OFF_W1);
    __half* s_W2   = (__half*)(scratch + OFF_W2);

    cudaFuncSetAttribute(attn_kernel, cudaFuncAttributeMaxDynamicSharedMemorySize, ATTN_SMEM);
    cudaFuncSetAttribute(tc_gemm<0>, cudaFuncAttributeMaxDynamicSharedMemorySize, GEMM_SMEM);
    cudaFuncSetAttribute(tc_gemm<1>, cudaFuncAttributeMaxDynamicSharedMemorySize, GEMM_SMEM);
    cudaFuncSetAttribute(tc_gemm<2>, cudaFuncAttributeMaxDynamicSharedMemorySize, GEMM_SMEM);

    // R14-proven stream footprint: default + s2 (weights) + s3 (second compute chain)
    static cudaStream_t s2 = nullptr, s3 = nullptr;
    static cudaEvent_t evFork = nullptr, evW = nullptr, evP = nullptr, evB = nullptr;
    if (s2 == nullptr) {
        cudaStreamCreateWithFlags(&s2, cudaStreamNonBlocking);
        cudaStreamCreateWithFlags(&s3, cudaStreamNonBlocking);
        cudaEventCreateWithFlags(&evFork, cudaEventDisableTiming);
        cudaEventCreateWithFlags(&evW, cudaEventDisableTiming);
        cudaEventCreateWithFlags(&evP, cudaEventDisableTiming);
        cudaEventCreateWithFlags(&evB, cudaEventDisableTiming);
    }

    // fork side streams off the capture stream
    cudaEventRecord(evFork, 0);
    cudaStreamWaitEvent(s2, evFork, 0);
    cudaStreamWaitEvent(s3, evFork, 0);

    // s2: independent weight transposes
    transpose_half<<<dim3(DD / 64, DD / 64), 256, 0, s2>>>(Wo, s_Wo, DD, DD);
    transpose_half<<<dim3(FF / 64, DD / 64), 256, 0, s2>>>(W1, s_W1, DD, FF);
    transpose_half<<<dim3(DD / 64, FF / 64), 256, 0, s2>>>(W2, s_W2, FF, DD);
    cudaEventRecord(evW, s2);

    // default: QKV weight pack (needed by all chains)
    pack_qkvT<<<dim3(DD / 64, 3 * DD / 64), 256>>>(Wq, Wk, Wv, s_Wqkv, bq, bk, bv, s_bqkv);
    cudaEventRecord(evP, 0);
    cudaStreamWaitEvent(s3, evP, 0);

    // 4 per-batch chains: chain i on stream (i&1) ? s3 : default
    bool waitedW[2] = {false, false};
    for (int i = 0; i < 4; i++) {
        cudaStream_t st = (i & 1) ? s3 : (cudaStream_t)0;
        const size_t r0 = (size_t)i * MQ;
        // head: LN1 -> QKV -> attention
        layernorm_kernel<<<MQ, 256, 0, st>>>(x + r0 * DD, ln1_g, ln1_b, s_h + r0 * DD);
        tc_gemm<0><<<dim3(3 * DD / GBN, MQ / GBM), 128, GEMM_SMEM, st>>>(
            s_h + r0 * DD, s_Wqkv, s_bqkv, nullptr, s_qkv + r0 * 3 * DD, MQ, 3 * DD, DD);
        attn_kernel<<<dim3(TT / 64, HH, 1), 128, ATTN_SMEM, st>>>(s_qkv, s_ctx, i);
        // wait for transposed weights (once per stream)
        if (!waitedW[i & 1]) { cudaStreamWaitEvent(st, evW, 0); waitedW[i & 1] = true; }
        // tail: Wo -> LN2 -> FFN1 -> FFN2
        tc_gemm<1><<<dim3(DD / GBN, MQ / GBM), 128, GEMM_SMEM, st>>>(
            s_ctx + r0 * DD, s_Wo, bo, x + r0 * DD, s_x1 + r0 * DD, MQ, DD, DD);
        layernorm_kernel<<<MQ, 256, 0, st>>>(s_x1 + r0 * DD, ln2_g, ln2_b, s_h2 + r0 * DD);
        tc_gemm<2><<<dim3(FF / GBN, MQ / GBM), 128, GEMM_SMEM, st>>>(
            s_h2 + r0 * DD, s_W1, b1, nullptr, s_ff + r0 * FF, MQ, FF, DD);
        tc_gemm<1><<<dim3(DD / GBN, MQ / GBM), 128, GEMM_SMEM, st>>>(
            s_ff + r0 * FF, s_W2, b2, s_x1 + r0 * DD, out + r0 * DD, MQ, DD, FF);
    }
    cudaEventRecord(evB, s3);

    // join s3 back into the capture stream
    cudaStreamWaitEvent(0, evB, 0);
}

// round 17
// speedup vs baseline: 1.0518x; 1.0518x over previous
#include <cuda_runtime.h>
#include <cuda_fp16.h>
#include <cstdint>
#include <math.h>

// ---------------- problem constants ----------------
#define BB 4
#define TT 2048
#define DD 1024
#define HH 16
#define HD 64
#define FF 4096
#define MM (BB*TT)          // 8192 rows
#define MHALF (MM/2)        // 4096 rows (2 batches per stream)

// ---------------- scratch arena (float units; half buffers cast in) ----------------
#define OFF_H     0                     // [MM,DD] half
#define OFF_QKV   4194304               // [MM,3DD] half
#define OFF_CTX   16777216              // [MM,DD] half
#define OFF_X1    20971520              // [MM,DD] float
#define OFF_H2    29360128              // [MM,DD] half
#define OFF_FF    33554432              // [MM,FF] half
#define OFF_WQKV  50331648              // [3DD,DD] half (transposed)
#define OFF_BQKV  51904512              // [3DD] float
#define OFF_WO    51907584              // [DD,DD] half (transposed)
#define OFF_W1    52431872              // [FF,DD] half (transposed)
#define OFF_W2    54529024              // [DD,FF] half (transposed)
#define SCRATCH_TOTAL 56626176

__device__ float d_scratch[SCRATCH_TOTAL];

// ---------------- helpers ----------------
__device__ __forceinline__ uint32_t smem_u32(const void* p) {
    uint32_t a;
    asm("{ .reg .u64 t; cvta.to.shared.u64 t, %1; cvt.u32.u64 %0, t; }" : "=r"(a) : "l"(p));
    return a;
}
__device__ __forceinline__ void cpasync16(uint32_t saddr, const void* g) {
    asm volatile("cp.async.cg.shared.global [%0], [%1], 16;" :: "r"(saddr), "l"(g));
}
__device__ __forceinline__ void ldsm_x4(uint32_t* r, uint32_t addr) {
    asm volatile("ldmatrix.sync.aligned.m8n8.x4.shared.b16 {%0,%1,%2,%3}, [%4];"
                 : "=r"(r[0]), "=r"(r[1]), "=r"(r[2]), "=r"(r[3]) : "r"(addr));
}
__device__ __forceinline__ void ldsm_x4_t(uint32_t* r, uint32_t addr) {
    asm volatile("ldmatrix.sync.aligned.m8n8.x4.trans.shared.b16 {%0,%1,%2,%3}, [%4];"
                 : "=r"(r[0]), "=r"(r[1]), "=r"(r[2]), "=r"(r[3]) : "r"(addr));
}
__device__ __forceinline__ void mma_f16(float* d, const uint32_t* a, uint32_t b0, uint32_t b1) {
    asm volatile("mma.sync.aligned.m16n8k16.row.col.f32.f16.f16.f32 "
                 "{%0,%1,%2,%3}, {%4,%5,%6,%7}, {%8,%9}, {%0,%1,%2,%3};"
                 : "+f"(d[0]), "+f"(d[1]), "+f"(d[2]), "+f"(d[3])
                 : "r"(a[0]), "r"(a[1]), "r"(a[2]), "r"(a[3]), "r"(b0), "r"(b1));
}
__device__ __forceinline__ uint32_t f22h2(float a, float b) {
    __half2 h = __floats2half2_rn(a, b);
    return *(uint32_t*)&h;
}
#define SWZ128(o) ((o) ^ (((o) >> 3) & 0x70))
#define QSCALE (0.125f * 1.44269504088896341f)   // 1/sqrt(HD) * log2(e)

// ---------------- fast 64x64-tile transpose to half ----------------
__global__ __launch_bounds__(256)
void transpose_half(const float* __restrict__ in, __half* __restrict__ out, int R, int C) {
    __shared__ float t[64][65];
    int c0 = blockIdx.x * 64, r0 = blockIdx.y * 64;
    int tid = threadIdx.x;
#pragma unroll
    for (int i = 0; i < 4; i++) {
        int idx = tid + i * 256;
        int r = idx >> 4, q = idx & 15;
        float4 v = *(const float4*)(in + (size_t)(r0 + r) * C + c0 + q * 4);
        t[r][q * 4 + 0] = v.x; t[r][q * 4 + 1] = v.y;
        t[r][q * 4 + 2] = v.z; t[r][q * 4 + 3] = v.w;
    }
    __syncthreads();
    int c = tid >> 2;
    int jb = (tid & 3) * 16;
    __half* orow = out + (size_t)(c0 + c) * R + r0 + jb;
#pragma unroll
    for (int u = 0; u < 8; u++) {
        *(uint32_t*)(orow + u * 2) = f22h2(t[jb + u * 2][c], t[jb + u * 2 + 1][c]);
    }
}

// ---------------- QKV weight pack + bias; Q scaled by QSCALE ----------------
__global__ __launch_bounds__(256)
void pack_qkvT(const float* __restrict__ Wq, const float* __restrict__ Wk,
               const float* __restrict__ Wv, __half* __restrict__ WqkvT,
               const float* __restrict__ bq, const float* __restrict__ bk,
               const float* __restrict__ bv, float* __restrict__ bqkv) {
    __shared__ float t[64][65];
    int n0 = blockIdx.y * 64;
    int d0 = blockIdx.x * 64;
    int proj = n0 >> 10;
    int h = (n0 & 1023) >> 6;
    const float* W = (proj == 0) ? Wq : ((proj == 1) ? Wk : Wv);
    float scale = (proj == 0) ? QSCALE : 1.0f;
    const float* base = W + (size_t)h * DD * HD;
    int tid = threadIdx.x;

    if (blockIdx.x == 0 && tid < 64) {
        const float* b = (proj == 0) ? bq : ((proj == 1) ? bk : bv);
        bqkv[n0 + tid] = b[(n0 & 1023) + tid] * scale;
    }

#pragma unroll
    for (int i = 0; i < 4; i++) {
        int idx = tid + i * 256;
        int r = idx >> 4, q = idx & 15;
        float4 v = *(const float4*)(base + (size_t)(d0 + r) * HD + q * 4);
        t[r][q * 4 + 0] = v.x * scale; t[r][q * 4 + 1] = v.y * scale;
        t[r][q * 4 + 2] = v.z * scale; t[r][q * 4 + 3] = v.w * scale;
    }
    __syncthreads();
    int c = tid >> 2;
    int jb = (tid & 3) * 16;
    __half* orow = WqkvT + (size_t)(n0 + c) * DD + d0 + jb;
#pragma unroll
    for (int u = 0; u < 8; u++) {
        *(uint32_t*)(orow + u * 2) = f22h2(t[jb + u * 2][c], t[jb + u * 2 + 1][c]);
    }
}

// ---------------- LayerNorm: fp32 in, half out ----------------
__global__ __launch_bounds__(256)
void layernorm_kernel(const float* __restrict__ x, const float* __restrict__ g,
                      const float* __restrict__ bta, __half* __restrict__ out) {
    __shared__ float red[16];
    int row = blockIdx.x;
    const float* xr = x + (size_t)row * DD;
    float v[4];
    float s = 0.f, s2 = 0.f;
#pragma unroll
    for (int i = 0; i < 4; i++) {
        v[i] = xr[threadIdx.x + i * 256];
        s += v[i];
        s2 += v[i] * v[i];
    }
#pragma unroll
    for (int o = 16; o > 0; o >>= 1) {
        s  += __shfl_xor_sync(0xffffffffu, s,  o);
        s2 += __shfl_xor_sync(0xffffffffu, s2, o);
    }
    int w = threadIdx.x >> 5;
    if ((threadIdx.x & 31) == 0) { red[w] = s; red[w + 8] = s2; }
    __syncthreads();
    s = 0.f; s2 = 0.f;
#pragma unroll
    for (int i = 0; i < 8; i++) { s += red[i]; s2 += red[i + 8]; }
    float mu  = s * (1.f / (float)DD);
    float var = s2 * (1.f / (float)DD) - mu * mu;
    float inv = rsqrtf(var + 1e-5f);
#pragma unroll
    for (int i = 0; i < 4; i++) {
        int c = threadIdx.x + i * 256;
        out[(size_t)row * DD + c] = __float2half_rn((v[i] - mu) * inv * g[c] + bta[c]);
    }
}

// ---------------- fp16 mma GEMM: BM=64,BN=128,BK=64, 128 thr, 2-stage, 4 CTA/SM ----------
#define GSTAGES 2
#define GBM 64
#define GBN 128
#define GBK 64
#define A_ST_BYTES (GBM * 128)           // 8192
#define B_ST_BYTES (GBN * 128)           // 16384
#define GEMM_SMEM (GSTAGES * (A_ST_BYTES + B_ST_BYTES))   // 49152

template <int EPI>
__global__ __launch_bounds__(128, 4)
void tc_gemm(const __half* __restrict__ A, const __half* __restrict__ BT,
             const float* __restrict__ bias, const float* __restrict__ res,
             void* __restrict__ Cout, int M, int N, int K) {
    extern __shared__ __align__(128) char smem[];
    uint32_t sb = smem_u32(smem);
    const uint32_t sA0 = sb;
    const uint32_t sB0 = sb + GSTAGES * A_ST_BYTES;

    int tid = threadIdx.x;
    int lane = tid & 31;
    int wn = tid >> 5;
    int bm = blockIdx.y * GBM, bn = blockIdx.x * GBN;

    int rowin = lane & 7;
    int quad  = lane >> 3;
    int lrow  = (quad & 1) * 8 + rowin;
    int lkoff = (quad >> 1) * 16;

    float acc[16][4];
#pragma unroll
    for (int i = 0; i < 16; i++)
#pragma unroll
        for (int j = 0; j < 4; j++) acc[i][j] = 0.f;

    const int NC = K / GBK;

    auto load_chunk = [&](int c) {
        int s = c & 1;
        uint32_t sA = sA0 + s * A_ST_BYTES;
        uint32_t sB = sB0 + s * B_ST_BYTES;
        const __half* Ab = A + (size_t)bm * K + c * GBK;
        const __half* Bb = BT + (size_t)bn * K + c * GBK;
#pragma unroll
        for (int i = 0; i < 4; i++) {
            int idx = tid + i * 128;
            int r = idx >> 3, q = idx & 7;
            cpasync16(sA + SWZ128((uint32_t)(r * 128 + q * 16)), Ab + (size_t)r * K + q * 8);
        }
#pragma unroll
        for (int i = 0; i < 8; i++) {
            int idx = tid + i * 128;
            int r = idx >> 3, q = idx & 7;
            cpasync16(sB + SWZ128((uint32_t)(r * 128 + q * 16)), Bb + (size_t)r * K + q * 8);
        }
        asm volatile("cp.async.commit_group;" ::: "memory");
    };

    load_chunk(0);
    load_chunk(1);

    for (int c = 0; c < NC; c++) {
        if (c + 1 < NC) asm volatile("cp.async.wait_group 1;" ::: "memory");
        else            asm volatile("cp.async.wait_group 0;" ::: "memory");
        __syncthreads();

        int s = c & 1;
        uint32_t aT = sA0 + s * A_ST_BYTES;
        uint32_t bT = sB0 + s * B_ST_BYTES;
#pragma unroll
        for (int ks = 0; ks < 4; ks++) {
            uint32_t af[4][4];
#pragma unroll
            for (int mi = 0; mi < 4; mi++) {
                uint32_t off = (uint32_t)((mi * 16 + lrow) * 128 + lkoff + ks * 32);
                ldsm_x4(af[mi], aT + SWZ128(off));
            }
            uint32_t bf[2][4];
#pragma unroll
            for (int np = 0; np < 2; np++) {
                uint32_t off = (uint32_t)((wn * 32 + np * 16 + lrow) * 128 + lkoff + ks * 32);
                ldsm_x4(bf[np], bT + SWZ128(off));
            }
#pragma unroll
            for (int mi = 0; mi < 4; mi++)
#pragma unroll
                for (int ni = 0; ni < 4; ni++) {
                    int np = ni >> 1, sub = ni & 1;
                    mma_f16(acc[mi * 4 + ni], af[mi], bf[np][sub], bf[np][sub + 2]);
                }
        }
        __syncthreads();
        if (c + 2 < NC) load_chunk(c + 2);
    }

#pragma unroll
    for (int mi = 0; mi < 4; mi++) {
        int r0 = bm + mi * 16 + (lane >> 2);
#pragma unroll
        for (int ni = 0; ni < 4; ni++) {
            int col = bn + wn * 32 + ni * 8 + 2 * (lane & 3);
            float2 bb = *(const float2*)(bias + col);
#pragma unroll
            for (int half_ = 0; half_ < 2; half_++) {
                int r = r0 + half_ * 8;
                float v0 = acc[mi * 4 + ni][half_ * 2 + 0] + bb.x;
                float v1 = acc[mi * 4 + ni][half_ * 2 + 1] + bb.y;
                if (EPI == 1) {
                    float2 rr = *(const float2*)(res + (size_t)r * N + col);
                    v0 += rr.x; v1 += rr.y;
                    *(float2*)((float*)Cout + (size_t)r * N + col) = make_float2(v0, v1);
                } else if (EPI == 2) {
                    v0 = 0.5f * v0 * (1.0f + erff(v0 * 0.70710678118654752f));
                    v1 = 0.5f * v1 * (1.0f + erff(v1 * 0.70710678118654752f));
                    *(uint32_t*)((__half*)Cout + (size_t)r * N + col) = f22h2(v0, v1);
                } else {
                    *(uint32_t*)((__half*)Cout + (size_t)r * N + col) = f22h2(v0, v1);
                }
            }
        }
    }
}

// ---------------- Flash attention: base-2 softmax, LPT, batch-offset ------------------------
#define ATTN_SMEM (8192 + 2 * 16384)
#define SQ_OFF 0
#define SK_OFF(s) (8192 + (s) * 16384)
#define SV_OFF(s) (16384 + (s) * 16384)

__global__ __launch_bounds__(128)
void attn_kernel(const __half* __restrict__ qkv, __half* __restrict__ ctx, int b0) {
    extern __shared__ __align__(128) char smem[];
    uint32_t sb = smem_u32(smem);

    int qt = gridDim.x - 1 - blockIdx.x;    // LPT: longest tiles first
    int h = blockIdx.y, b = blockIdx.z + b0;
    int tid = threadIdx.x;
    int lane = tid & 31;
    int warp = tid >> 5;
    int q0 = qt * 64;

    int rowin = lane & 7;
    int quad  = lane >> 3;
    int lrow  = (quad & 1) * 8 + rowin;
    int lkoff = (quad >> 1) * 16;
    int g = lane >> 2;
    int t2 = 2 * (lane & 3);

    const __half* qbase = qkv + (size_t)(b * TT + q0) * 3072 + h * 64;
#pragma unroll
    for (int i = 0; i < 4; i++) {
        int idx = tid + i * 128;
        int r = idx >> 3, q = idx & 7;
        cpasync16(sb + SQ_OFF + SWZ128((uint32_t)(r * 128 + q * 16)),
                  qbase + (size_t)r * 3072 + q * 8);
    }
    auto load_kv = [&](int jt) {
        int s = jt & 1;
        const __half* kb = qkv + (size_t)(b * TT + jt * 64) * 3072 + 1024 + h * 64;
        const __half* vb = kb + 1024;
#pragma unroll
        for (int i = 0; i < 4; i++) {
            int idx = tid + i * 128;
            int r = idx >> 3, q = idx & 7;
            uint32_t off = SWZ128((uint32_t)(r * 128 + q * 16));
            cpasync16(sb + SK_OFF(s) + off, kb + (size_t)r * 3072 + q * 8);
            cpasync16(sb + SV_OFF(s) + off, vb + (size_t)r * 3072 + q * 8);
        }
        asm volatile("cp.async.commit_group;" ::: "memory");
    };
    load_kv(0);

    float m0 = -1e30f, m1 = -1e30f, l0 = 0.f, l1 = 0.f;
    float accO[8][4];
#pragma unroll
    for (int i = 0; i < 8; i++)
#pragma unroll
        for (int j = 0; j < 4; j++) accO[i][j] = 0.f;

    uint32_t qaf[4][4];
    bool qloaded = false;

    for (int jt = 0; jt <= qt; jt++) {
        if (jt + 1 <= qt) load_kv(jt + 1);
        if (jt + 1 <= qt) asm volatile("cp.async.wait_group 1;" ::: "memory");
        else              asm volatile("cp.async.wait_group 0;" ::: "memory");
        __syncthreads();

        int s = jt & 1;
        uint32_t kT = sb + SK_OFF(s);
        uint32_t vT = sb + SV_OFF(s);

        if (!qloaded) {
            qloaded = true;
#pragma unroll
            for (int ks = 0; ks < 4; ks++) {
                uint32_t off = (uint32_t)((warp * 16 + lrow) * 128 + lkoff + ks * 32);
                ldsm_x4(qaf[ks], sb + SQ_OFF + SWZ128(off));
            }
        }

        float sc[8][4];
#pragma unroll
        for (int i = 0; i < 8; i++)
#pragma unroll
            for (int j = 0; j < 4; j++) sc[i][j] = 0.f;
#pragma unroll
        for (int ks = 0; ks < 4; ks++) {
#pragma unroll
            for (int np = 0; np < 4; np++) {
                uint32_t bf[4];
                uint32_t off = (uint32_t)((np * 16 + lrow) * 128 + lkoff + ks * 32);
                ldsm_x4(bf, kT + SWZ128(off));
                mma_f16(sc[np * 2 + 0], qaf[ks], bf[0], bf[2]);
                mma_f16(sc[np * 2 + 1], qaf[ks], bf[1], bf[3]);
            }
        }

        if (jt == qt) {
            int r0g = warp * 16 + g, r1g = r0g + 8;
#pragma unroll
            for (int i = 0; i < 8; i++) {
                int c0 = i * 8 + t2;
                if (c0     > r0g) sc[i][0] = -1e30f;
                if (c0 + 1 > r0g) sc[i][1] = -1e30f;
                if (c0     > r1g) sc[i][2] = -1e30f;
                if (c0 + 1 > r1g) sc[i][3] = -1e30f;
            }
        }

        float mx0 = -1e30f, mx1 = -1e30f;
#pragma unroll
        for (int i = 0; i < 8; i++) {
            mx0 = fmaxf(mx0, fmaxf(sc[i][0], sc[i][1]));
            mx1 = fmaxf(mx1, fmaxf(sc[i][2], sc[i][3]));
        }
#pragma unroll
        for (int o = 1; o <= 2; o <<= 1) {
            mx0 = fmaxf(mx0, __shfl_xor_sync(0xffffffffu, mx0, o));
            mx1 = fmaxf(mx1, __shfl_xor_sync(0xffffffffu, mx1, o));
        }
        float mn0 = fmaxf(m0, mx0), mn1 = fmaxf(m1, mx1);
        float sc0 = exp2f(m0 - mn0), sc1 = exp2f(m1 - mn1);
        float sum0 = 0.f, sum1 = 0.f;
        uint32_t ph[8][2];
#pragma unroll
        for (int i = 0; i < 8; i++) {
            float p0 = exp2f(sc[i][0] - mn0);
            float p1 = exp2f(sc[i][1] - mn0);
            float p2 = exp2f(sc[i][2] - mn1);
            float p3 = exp2f(sc[i][3] - mn1);
            sum0 += p0 + p1; sum1 += p2 + p3;
            ph[i][0] = f22h2(p0, p1);
            ph[i][1] = f22h2(p2, p3);
        }
#pragma unroll
        for (int o = 1; o <= 2; o <<= 1) {
            sum0 += __shfl_xor_sync(0xffffffffu, sum0, o);
            sum1 += __shfl_xor_sync(0xffffffffu, sum1, o);
        }
        l0 = l0 * sc0 + sum0; l1 = l1 * sc1 + sum1;
        m0 = mn0; m1 = mn1;
#pragma unroll
        for (int i = 0; i < 8; i++) {
            accO[i][0] *= sc0; accO[i][1] *= sc0;
            accO[i][2] *= sc1; accO[i][3] *= sc1;
        }

#pragma unroll
        for (int kt = 0; kt < 4; kt++) {
            uint32_t pa[4] = { ph[2 * kt][0], ph[2 * kt][1], ph[2 * kt + 1][0], ph[2 * kt + 1][1] };
#pragma unroll
            for (int dg = 0; dg < 4; dg++) {
                uint32_t bf[4];
                uint32_t off = (uint32_t)((kt * 16 + lrow) * 128 + dg * 32 + lkoff);
                ldsm_x4_t(bf, vT + SWZ128(off));
                mma_f16(accO[dg * 2 + 0], pa, bf[0], bf[1]);
                mma_f16(accO[dg * 2 + 1], pa, bf[2], bf[3]);
            }
        }
        __syncthreads();
    }

    float inv0 = 1.f / l0, inv1 = 1.f / l1;
    int r0 = b * TT + q0 + warp * 16 + g;
#pragma unroll
    for (int i = 0; i < 8; i++) {
        int col = h * 64 + i * 8 + t2;
        *(uint32_t*)(ctx + (size_t)r0 * DD + col)       = f22h2(accO[i][0] * inv0, accO[i][1] * inv0);
        *(uint32_t*)(ctx + (size_t)(r0 + 8) * DD + col) = f22h2(accO[i][2] * inv1, accO[i][3] * inv1);
    }
}

// ---------------- launcher: two row-half chains; all weight prep on s2 ----------------
extern "C" void kernel_launch(void* const* d_in, const int* in_sizes, int n_in,
                              void* d_out, int out_size) {
    const float* x     = (const float*)d_in[0];
    const float* ln1_g = (const float*)d_in[2];
    const float* ln1_b = (const float*)d_in[3];
    const float* Wq    = (const float*)d_in[4];
    const float* bq    = (const float*)d_in[5];
    const float* Wk    = (const float*)d_in[6];
    const float* bk    = (const float*)d_in[7];
    const float* Wv    = (const float*)d_in[8];
    const float* bv    = (const float*)d_in[9];
    const float* Wo    = (const float*)d_in[10];
    const float* bo    = (const float*)d_in[11];
    const float* ln2_g = (const float*)d_in[12];
    const float* ln2_b = (const float*)d_in[13];
    const float* W1    = (const float*)d_in[14];
    const float* b1    = (const float*)d_in[15];
    const float* W2    = (const float*)d_in[16];
    const float* b2    = (const float*)d_in[17];
    float* out = (float*)d_out;

    float* scratch = nullptr;
    cudaGetSymbolAddress((void**)&scratch, d_scratch);
    __half* s_h    = (__half*)(scratch + OFF_H);
    __half* s_qkv  = (__half*)(scratch + OFF_QKV);
    __half* s_ctx  = (__half*)(scratch + OFF_CTX);
    float*  s_x1   = scratch + OFF_X1;
    __half* s_h2   = (__half*)(scratch + OFF_H2);
    __half* s_ff   = (__half*)(scratch + OFF_FF);
    __half* s_Wqkv = (__half*)(scratch + OFF_WQKV);
    float*  s_bqkv = scratch + OFF_BQKV;
    __half* s_Wo   = (__half*)(scratch + OFF_WO);
    __half* s_W1   = (__half*)(scratch + OFF_W1);
    __half* s_W2   = (__half*)(scratch + OFF_W2);

    cudaFuncSetAttribute(attn_kernel, cudaFuncAttributeMaxDynamicSharedMemorySize, ATTN_SMEM);
    cudaFuncSetAttribute(tc_gemm<0>, cudaFuncAttributeMaxDynamicSharedMemorySize, GEMM_SMEM);
    cudaFuncSetAttribute(tc_gemm<1>, cudaFuncAttributeMaxDynamicSharedMemorySize, GEMM_SMEM);
    cudaFuncSetAttribute(tc_gemm<2>, cudaFuncAttributeMaxDynamicSharedMemorySize, GEMM_SMEM);

    static cudaStream_t s2 = nullptr, s3 = nullptr;
    static cudaEvent_t evFork = nullptr, evW = nullptr, evP = nullptr, evB = nullptr;
    if (s2 == nullptr) {
        cudaStreamCreateWithFlags(&s2, cudaStreamNonBlocking);
        cudaStreamCreateWithFlags(&s3, cudaStreamNonBlocking);
        cudaEventCreateWithFlags(&evFork, cudaEventDisableTiming);
        cudaEventCreateWithFlags(&evW, cudaEventDisableTiming);
        cudaEventCreateWithFlags(&evP, cudaEventDisableTiming);
        cudaEventCreateWithFlags(&evB, cudaEventDisableTiming);
    }

    // fork both side streams off the capture stream
    cudaEventRecord(evFork, 0);
    cudaStreamWaitEvent(s2, evFork, 0);
    cudaStreamWaitEvent(s3, evFork, 0);

    // s2: ALL weight prep (QKV pack first: it gates the QKV GEMMs; transposes after)
    pack_qkvT<<<dim3(DD / 64, 3 * DD / 64), 256, 0, s2>>>(Wq, Wk, Wv, s_Wqkv, bq, bk, bv, s_bqkv);
    cudaEventRecord(evP, s2);
    transpose_half<<<dim3(DD / 64, DD / 64), 256, 0, s2>>>(Wo, s_Wo, DD, DD);
    transpose_half<<<dim3(FF / 64, DD / 64), 256, 0, s2>>>(W1, s_W1, DD, FF);
    transpose_half<<<dim3(DD / 64, FF / 64), 256, 0, s2>>>(W2, s_W2, FF, DD);
    cudaEventRecord(evW, s2);

    // per-half chains: half 0 = rows [0, MHALF) on default, half 1 on s3
    const size_t r1 = MHALF;

    // ---- half 0 head (default stream): LN1 starts immediately, pack overlaps ----
    layernorm_kernel<<<MHALF, 256>>>(x, ln1_g, ln1_b, s_h);
    cudaStreamWaitEvent(0, evP, 0);
    tc_gemm<0><<<dim3(3 * DD / GBN, MHALF / GBM), 128, GEMM_SMEM>>>(
        s_h, s_Wqkv, s_bqkv, nullptr, s_qkv, MHALF, 3 * DD, DD);
    attn_kernel<<<dim3(TT / 64, HH, BB / 2), 128, ATTN_SMEM>>>(s_qkv, s_ctx, 0);

    // ---- half 1 head (s3) ----
    layernorm_kernel<<<MHALF, 256, 0, s3>>>(x + r1 * DD, ln1_g, ln1_b, s_h + r1 * DD);
    cudaStreamWaitEvent(s3, evP, 0);
    tc_gemm<0><<<dim3(3 * DD / GBN, MHALF / GBM), 128, GEMM_SMEM, s3>>>(
        s_h + r1 * DD, s_Wqkv, s_bqkv, nullptr, s_qkv + r1 * 3 * DD, MHALF, 3 * DD, DD);
    attn_kernel<<<dim3(TT / 64, HH, BB / 2), 128, ATTN_SMEM, s3>>>(s_qkv, s_ctx, BB / 2);

    // both halves need the transposed weights from here on
    cudaStreamWaitEvent(0, evW, 0);
    cudaStreamWaitEvent(s3, evW, 0);

    // ---- half 0 tail ----
    tc_gemm<1><<<dim3(DD / GBN, MHALF / GBM), 128, GEMM_SMEM>>>(
        s_ctx, s_Wo, bo, x, s_x1, MHALF, DD, DD);
    layernorm_kernel<<<MHALF, 256>>>(s_x1, ln2_g, ln2_b, s_h2);
    tc_gemm<2><<<dim3(FF / GBN, MHALF / GBM), 128, GEMM_SMEM>>>(
        s_h2, s_W1, b1, nullptr, s_ff, MHALF, FF, DD);
    tc_gemm<1><<<dim3(DD / GBN, MHALF / GBM), 128, GEMM_SMEM>>>(
        s_ff, s_W2, b2, s_x1, out, MHALF, DD, FF);

    // ---- half 1 tail (s3) ----
    tc_gemm<1><<<dim3(DD / GBN, MHALF / GBM), 128, GEMM_SMEM, s3>>>(
        s_ctx + r1 * DD, s_Wo, bo, x + r1 * DD, s_x1 + r1 * DD, MHALF, DD, DD);
    layernorm_kernel<<<MHALF, 256, 0, s3>>>(s_x1 + r1 * DD, ln2_g, ln2_b, s_h2 + r1 * DD);
    tc_gemm<2><<<dim3(FF / GBN, MHALF / GBM), 128, GEMM_SMEM, s3>>>(
        s_h2 + r1 * DD, s_W1, b1, nullptr, s_ff + r1 * FF, MHALF, FF, DD);
    tc_gemm<1><<<dim3(DD / GBN, MHALF / GBM), 128, GEMM_SMEM, s3>>>(
        s_ff + r1 * FF, s_W2, b2, s_x1 + r1 * DD, out + r1 * DD, MHALF, DD, FF);
    cudaEventRecord(evB, s3);

    // join half 1 back into the capture stream
    cudaStreamWaitEvent(0, evB, 0);
}